// round 9
// baseline (speedup 1.0000x reference)
#include <cuda_runtime.h>
#include <cuda_bf16.h>
#include <cstdint>

#define NCAT 20
#define NNUM 20
#define EMBD 32
#define HID  128
#define NMOD 50
#define NTHR 256

typedef unsigned long long u64;
typedef unsigned int u32;

// ---------------- smem layout ----------------
#define BSTR  136                       // bf16 per BT row (272 B)
#define SSTR  130                       // f32 per staging row
#define OB    0                         // 6 * 128 * 272 = 208896 B
#define OST   208896                    // staging 32 * 130 * 4 = 16640 B
#define OXS   225536                    // x chunk 32 * 40 * 4 = 5120 B
#define OD    230656                    // 384 * 4 = 1536 B
#define SMEM_REQ 232192                 // <= 232448 max

// ---------------- device scratch ----------------
__device__ float g_Tcat[NCAT * NMOD * HID];
__device__ float g_vnum[NNUM * HID];
__device__ float g_base[HID];
__device__ float g_d[3 * HID];
__device__ __align__(16) unsigned short g_B[6 * HID * BSTR];   // BT[n][k], padded rows

// ---------------- helpers ----------------
__device__ __forceinline__ u64 dup2(float a) {
    u64 r; asm("mov.b64 %0,{%1,%1};" : "=l"(r) : "f"(a)); return r;
}
__device__ __forceinline__ float2 upk2(u64 v) {
    float2 f; asm("mov.b64 {%0,%1},%2;" : "=f"(f.x), "=f"(f.y) : "l"(v)); return f;
}
__device__ __forceinline__ u64 fma2(u64 a, u64 b, u64 c) {
    u64 d; asm("fma.rn.f32x2 %0,%1,%2,%3;" : "=l"(d) : "l"(a), "l"(b), "l"(c)); return d;
}
__device__ __forceinline__ u64 add2(u64 a, u64 b) {
    u64 d; asm("add.rn.f32x2 %0,%1,%2;" : "=l"(d) : "l"(a), "l"(b)); return d;
}
__device__ __forceinline__ u32 cvt_bf2(float hi_val, float lo_val) {
    u32 w; asm("cvt.rn.bf16x2.f32 %0,%1,%2;" : "=r"(w) : "f"(hi_val), "f"(lo_val)); return w;
}
__device__ __forceinline__ void split2(float c0, float c1, u32& hi, u32& lo) {
    hi = cvt_bf2(c1, c0);
    float e0 = c0 - __uint_as_float(hi << 16);
    float e1 = c1 - __uint_as_float(hi & 0xffff0000u);
    lo = cvt_bf2(e1, e0);
}
__device__ __forceinline__ u32 smem_u32(const void* p) {
    u32 a;
    asm("{ .reg .u64 t; cvta.to.shared.u64 t, %1; cvt.u32.u64 %0, t; }" : "=r"(a) : "l"(p));
    return a;
}

#define MMA(d, a, b0v, b1v) \
    asm volatile("mma.sync.aligned.m16n8k16.row.col.f32.bf16.bf16.f32 " \
        "{%0,%1,%2,%3},{%4,%5,%6,%7},{%8,%9},{%0,%1,%2,%3};" \
        : "+f"((d)[0]), "+f"((d)[1]), "+f"((d)[2]), "+f"((d)[3]) \
        : "r"((a)[0]), "r"((a)[1]), "r"((a)[2]), "r"((a)[3]), "r"(b0v), "r"(b1v))

#define LDM4(r, addr) \
    asm volatile("ldmatrix.sync.aligned.m8n8.x4.shared.b16 {%0,%1,%2,%3}, [%4];" \
        : "=r"((r)[0]), "=r"((r)[1]), "=r"((r)[2]), "=r"((r)[3]) : "r"(addr))

// ---------------- precompute kernel ----------------
__global__ void pre_all_kernel(const float* __restrict__ emb,
                               const float* __restrict__ W_num, const float* __restrict__ b_num,
                               const float* __restrict__ W_in,  const float* __restrict__ b_in,
                               const float* __restrict__ W1,    const float* __restrict__ b1,
                               const float* __restrict__ W2,    const float* __restrict__ b2,
                               const float* __restrict__ ln_g,  const float* __restrict__ ln_b,
                               const float* __restrict__ W_out, const float* __restrict__ b_out) {
    const int b = blockIdx.x;
    const int j = threadIdx.x;
    if (b < NCAT * NMOD) {
        int fc = b, f = fc / NMOD;
        const float* e = emb + fc * EMBD;
        float s = 0.f;
#pragma unroll
        for (int k = 0; k < EMBD; k++) s += e[k] * W_in[(f * EMBD + k) * HID + j];
        g_Tcat[fc * HID + j] = s;
    } else if (b < NCAT * NMOD + 3 * HID) {
        int bx = b - NCAT * NMOD;
        int s = bx >> 7, k = bx & 127;
        float v;
        if (s == 2) {
            v = ln_g[HID + k] * W_out[k * HID + j];
        } else {
            const float* w1 = W1 + s * HID * 2 * HID + k * 2 * HID;
            const float* w2 = W2 + s * 2 * HID * HID;
            float acc = 0.f;
            for (int m = 0; m < 2 * HID; m++) acc += w1[m] * w2[m * HID + j];
            v = (s == 1) ? ln_g[k] * acc : acc;
        }
        __nv_bfloat16 h = __float2bfloat16(v);
        float rem = v - __bfloat162float(h);
        __nv_bfloat16 lo = __float2bfloat16(rem);
        g_B[(size_t)(s * 2 + 0) * HID * BSTR + j * BSTR + k] = *reinterpret_cast<unsigned short*>(&h);
        g_B[(size_t)(s * 2 + 1) * HID * BSTR + j * BSTR + k] = *reinterpret_cast<unsigned short*>(&lo);
    } else {
        for (int f = 0; f < NNUM; f++) {
            float s = 0.f;
#pragma unroll
            for (int k = 0; k < EMBD; k++)
                s += W_num[f * EMBD + k] * W_in[((NCAT + f) * EMBD + k) * HID + j];
            g_vnum[f * HID + j] = s;
        }
        float bb = b_in[j];
        for (int f = 0; f < NNUM; f++)
#pragma unroll
            for (int k = 0; k < EMBD; k++)
                bb += b_num[f * EMBD + k] * W_in[((NCAT + f) * EMBD + k) * HID + j];
        g_base[j] = bb;
        float d1 = b2[j];
        for (int m = 0; m < 2 * HID; m++) d1 += b1[m] * W2[m * HID + j];
        g_d[j] = d1;
        __shared__ float u[2 * HID];
        for (int m = j; m < 2 * HID; m += HID) {
            float s = 0.f;
            for (int k = 0; k < HID; k++)
                s += ln_b[k] * W1[HID * 2 * HID + k * 2 * HID + m];
            u[m] = s;
        }
        __syncthreads();
        float d2 = b2[HID + j];
        for (int m = 0; m < 2 * HID; m++)
            d2 += (u[m] + b1[2 * HID + m]) * W2[2 * HID * HID + m * HID + j];
        g_d[HID + j] = d2;
        float d3 = b_out[j];
        for (int k = 0; k < HID; k++) d3 += ln_b[HID + k] * W_out[k * HID + j];
        g_d[2 * HID + j] = d3;
    }
}

// ---------------- main fused kernel ----------------
__global__ __launch_bounds__(NTHR, 1)
void main_kernel(const float* __restrict__ x, float* __restrict__ out,
                 int nrows, int ntiles) {
    extern __shared__ __align__(16) char smem[];
    const u32 sbase = smem_u32(smem);
    const int t = threadIdx.x;
    const int w = t >> 5;
    const int l = t & 31;
    const int q = l >> 2;      // lane/4
    const int m = l & 3;       // lane%4

    // copy BT matrices and bias vectors
    {
        const float4* src = (const float4*)g_B;
        float4* dst = (float4*)(smem + OB);
        for (int i = t; i < 208896 / 16; i += NTHR) dst[i] = src[i];
        float* dd = (float*)(smem + OD);
        for (int i = t; i < 3 * HID; i += NTHR) dd[i] = g_d[i];
    }
    __syncthreads();

    float* stg = (float*)(smem + OST);
    float* xs  = (float*)(smem + OXS);
    const float* dsm = (const float*)(smem + OD);
    const u32 btb = sbase + OB;
    // per-lane ldmatrix row/group offset: row (l&7) of 8-row tile, group (l>>3) selects 16B k-chunk
    const u32 rowg = (u32)((l & 7) * 272 + (l >> 3) * 16);

    const u64* Tc = (const u64*)g_Tcat;
    const u64* Vn = (const u64*)g_vnum;
    const u64* Bs = (const u64*)g_base;
    const int p  = t & 63;     // embed: col pair 2p,2p+1
    const int rg = t >> 6;     // embed: row octet within 32-row chunk

    for (int tt = blockIdx.x; tt < ntiles; tt += gridDim.x) {
        const int row0 = tt * 128;

        // per-tile invariants
        u64 vn[NNUM];
#pragma unroll
        for (int f = 0; f < NNUM; f++) vn[f] = __ldg(Vn + f * 64 + p);
        const u64 bb = __ldg(Bs + p);

        // ============ embed 4 chunks of 32 rows ============
        u32 AH[8][4], AL[8][4];
        for (int c = 0; c < 4; c++) {
            const int crow = row0 + 32 * c;
            // stage x chunk (coalesced float4)
            {
                const float4* xg = (const float4*)x;
                float4* xd = (float4*)xs;
#pragma unroll
                for (int i = t; i < 320; i += NTHR) {
                    int r = i / 10, j2 = i - r * 10;
                    int rr = min(crow + r, nrows - 1);
                    xd[i] = xg[(size_t)rr * 10 + j2];
                }
            }
            __syncthreads();
            // embed: 2 accumulation chains per (row, colpair)
#pragma unroll 2
            for (int i = 0; i < 8; i++) {
                int r = rg * 8 + i;
                const float* xr = xs + r * 40;
                u64 aA = bb, aB = 0ull;
#pragma unroll
                for (int f = 0; f < 10; f++) {
                    int ia = (int)xr[f];
                    int ib = (int)xr[10 + f];
                    aA = add2(aA, __ldg(Tc + (f * NMOD + ia) * 64 + p));
                    aB = add2(aB, __ldg(Tc + ((10 + f) * NMOD + ib) * 64 + p));
                }
#pragma unroll
                for (int f = 0; f < 10; f++) {
                    aA = fma2(vn[f], dup2(xr[NCAT + f]), aA);
                    aB = fma2(vn[10 + f], dup2(xr[NCAT + 10 + f]), aB);
                }
                float2 v = upk2(add2(aA, aB));
                *(float2*)&stg[r * SSTR + 2 * p] = v;
            }
            __syncthreads();
            if ((w >> 1) == c) {
                const int rb = (w & 1) * 16 + q;
#pragma unroll
                for (int kt = 0; kt < 8; kt++) {
                    int c0 = 16 * kt + 2 * m;
                    float2 v00 = *(const float2*)&stg[rb * SSTR + c0];
                    float2 v10 = *(const float2*)&stg[(rb + 8) * SSTR + c0];
                    float2 v01 = *(const float2*)&stg[rb * SSTR + c0 + 8];
                    float2 v11 = *(const float2*)&stg[(rb + 8) * SSTR + c0 + 8];
                    split2(v00.x, v00.y, AH[kt][0], AL[kt][0]);
                    split2(v10.x, v10.y, AH[kt][1], AL[kt][1]);
                    split2(v01.x, v01.y, AH[kt][2], AL[kt][2]);
                    split2(v11.x, v11.y, AH[kt][3], AL[kt][3]);
                }
            }
            __syncthreads();
        }

        // ============ 3 MMA stages, warp-local, B via ldmatrix ============
        float D[16][4];
#pragma unroll 1
        for (int s = 0; s < 3; s++) {
            // bias init
#pragma unroll
            for (int nt = 0; nt < 16; nt++) {
                float2 bv = *(const float2*)&dsm[s * HID + nt * 8 + 2 * m];
                D[nt][0] = bv.x; D[nt][1] = bv.y; D[nt][2] = bv.x; D[nt][3] = bv.y;
            }
            const u32 B0u = btb + (u32)s * 69632u;
            const u32 B1u = B0u + 34816u;
#pragma unroll
            for (int ktp = 0; ktp < 4; ktp++) {
                const u32 aH0 = B0u + (u32)(ktp * 64) + rowg;
                const u32 aL0 = B1u + (u32)(ktp * 64) + rowg;
#pragma unroll
                for (int nt = 0; nt < 16; nt++) {
                    u32 h4[4], l4[4];
                    LDM4(h4, aH0 + nt * 2176);
                    LDM4(l4, aL0 + nt * 2176);
                    MMA(D[nt], AH[2 * ktp],     h4[0], h4[1]);
                    MMA(D[nt], AL[2 * ktp],     h4[0], h4[1]);
                    MMA(D[nt], AH[2 * ktp],     l4[0], l4[1]);
                    MMA(D[nt], AH[2 * ktp + 1], h4[2], h4[3]);
                    MMA(D[nt], AL[2 * ktp + 1], h4[2], h4[3]);
                    MMA(D[nt], AH[2 * ktp + 1], l4[2], l4[3]);
                }
            }

            if (s < 2) {
                // ---- LayerNorm (rows q and q+8): reduce across 4-lane m-group ----
                float s1a = 0.f, s2a = 0.f, s1b = 0.f, s2b = 0.f;
#pragma unroll
                for (int nt = 0; nt < 16; nt++) {
                    s1a += D[nt][0] + D[nt][1];
                    s2a += D[nt][0] * D[nt][0] + D[nt][1] * D[nt][1];
                    s1b += D[nt][2] + D[nt][3];
                    s2b += D[nt][2] * D[nt][2] + D[nt][3] * D[nt][3];
                }
#pragma unroll
                for (int off = 1; off <= 2; off <<= 1) {
                    s1a += __shfl_xor_sync(0xffffffffu, s1a, off);
                    s2a += __shfl_xor_sync(0xffffffffu, s2a, off);
                    s1b += __shfl_xor_sync(0xffffffffu, s1b, off);
                    s2b += __shfl_xor_sync(0xffffffffu, s2b, off);
                }
                const float inv = 1.f / HID;
                float mua = s1a * inv, mub = s1b * inv;
                float rsa = rsqrtf(s2a * inv - mua * mua + 1e-5f);
                float rsb = rsqrtf(s2b * inv - mub * mub + 1e-5f);
                float nma = -mua * rsa, nmb = -mub * rsb;
                // ---- D -> next-stage A fragments (register-only) ----
#pragma unroll
                for (int kt = 0; kt < 8; kt++) {
                    int n0 = 2 * kt, n1 = 2 * kt + 1;
                    split2(D[n0][0] * rsa + nma, D[n0][1] * rsa + nma, AH[kt][0], AL[kt][0]);
                    split2(D[n0][2] * rsb + nmb, D[n0][3] * rsb + nmb, AH[kt][1], AL[kt][1]);
                    split2(D[n1][0] * rsa + nma, D[n1][1] * rsa + nma, AH[kt][2], AL[kt][2]);
                    split2(D[n1][2] * rsb + nmb, D[n1][3] * rsb + nmb, AH[kt][3], AL[kt][3]);
                }
            } else {
                // ---- final store ----
                int ra = row0 + 16 * w + q;
                int rb2 = ra + 8;
#pragma unroll
                for (int nt = 0; nt < 16; nt++) {
                    int col = nt * 8 + 2 * m;
                    if (ra < nrows)
                        *(float2*)&out[(size_t)ra * HID + col] = make_float2(D[nt][0], D[nt][1]);
                    if (rb2 < nrows)
                        *(float2*)&out[(size_t)rb2 * HID + col] = make_float2(D[nt][2], D[nt][3]);
                }
            }
        }
    }
}

// ---------------- launch ----------------
extern "C" void kernel_launch(void* const* d_in, const int* in_sizes, int n_in,
                              void* d_out, int out_size) {
    const float* x     = (const float*)d_in[0];
    const float* emb   = (const float*)d_in[1];
    const float* W_num = (const float*)d_in[2];
    const float* b_num = (const float*)d_in[3];
    const float* W_in  = (const float*)d_in[4];
    const float* b_in  = (const float*)d_in[5];
    const float* W1    = (const float*)d_in[6];
    const float* b1    = (const float*)d_in[7];
    const float* W2    = (const float*)d_in[8];
    const float* b2    = (const float*)d_in[9];
    const float* ln_g  = (const float*)d_in[10];
    const float* ln_b  = (const float*)d_in[11];
    const float* W_out = (const float*)d_in[12];
    const float* b_out = (const float*)d_in[13];
    float* out = (float*)d_out;

    const int nrows  = in_sizes[0] / 40;
    const int ntiles = (nrows + 127) / 128;

    static int smem_set = 0;
    if (!smem_set) {
        cudaFuncSetAttribute(main_kernel, cudaFuncAttributeMaxDynamicSharedMemorySize,
                             SMEM_REQ);
        smem_set = 1;
    }

    pre_all_kernel<<<NCAT * NMOD + 3 * HID + 1, HID>>>(
        emb, W_num, b_num, W_in, b_in, W1, b1, W2, b2, ln_g, ln_b, W_out, b_out);
    main_kernel<<<148, NTHR, SMEM_REQ>>>(x, out, nrows, ntiles);
}